// round 5
// baseline (speedup 1.0000x reference)
#include <cuda_runtime.h>
#include <math.h>
#include <stdint.h>

// ---------------- problem constants ----------------
#define T_STEPS 64
#define BATCH   128
#define A_DIM   6
#define EMBED   1024
#define HDIM    1024
#define G3      3072
#define DIST    1024
#define NCHAIN  4
// JAX >= 0.5 default: threefry_partitionable = True  (bits = o0 ^ o1, counter (0,i))
#define JAX_PARTITIONABLE 1

// ---------------- device scratch (static: no allocation) ----------------
__device__ int   g_idx  [NCHAIN][BATCH][32];   // argmax index per (chain,b,group); -1 = zero state
__device__ float g_deter[NCHAIN][BATCH][HDIM];
__device__ float g_x    [NCHAIN][BATCH][HDIM];
__device__ float g_g    [NCHAIN][BATCH][G3];
__device__ float g_h1   [NCHAIN][BATCH][HDIM];
__device__ float g_stats[NCHAIN][BATCH][DIST];   // only chains 2,3 read back

// ---------------- threefry2x32 (exact JAX semantics) ----------------
__device__ __forceinline__ void tf2x32(unsigned k0, unsigned k1, unsigned x0, unsigned x1,
                                       unsigned& o0, unsigned& o1) {
  unsigned k2 = k0 ^ k1 ^ 0x1BD11BDAu;
  x0 += k0; x1 += k1;
#define TF_RND(r) { x0 += x1; x1 = (x1 << (r)) | (x1 >> (32 - (r))); x1 ^= x0; }
  TF_RND(13) TF_RND(15) TF_RND(26) TF_RND(6)
  x0 += k1; x1 += k2 + 1u;
  TF_RND(17) TF_RND(29) TF_RND(16) TF_RND(24)
  x0 += k2; x1 += k0 + 2u;
  TF_RND(13) TF_RND(15) TF_RND(26) TF_RND(6)
  x0 += k0; x1 += k1 + 3u;
  TF_RND(17) TF_RND(29) TF_RND(16) TF_RND(24)
  x0 += k1; x1 += k2 + 4u;
  TF_RND(13) TF_RND(15) TF_RND(26) TF_RND(6)
  x0 += k2; x1 += k0 + 5u;
#undef TF_RND
  o0 = x0; o1 = x1;
}

// ---------------- pre layer: x = elu(gather(w_pre, idx) + act @ w_pre[1024:] + b_pre) ----
// stoch is exactly one-hot per 32-group (straight-through forward value), so
// stoch @ w_pre[:1024] == sum of the 32 selected rows in ascending group order.
// idx=-1 (initial zero state) => zero contribution.
__global__ __launch_bounds__(256) void pre_k(const float* __restrict__ act_t,
                                             const float* __restrict__ w_pre,
                                             const float* __restrict__ b_pre) {
  const int row = blockIdx.x;            // 0..511
  const int chain = row >> 7, b = row & 127;
  const int col = threadIdx.x * 4;       // 256 threads * 4 = 1024 cols

  __shared__ int   sidx[32];
  __shared__ float sact[A_DIM];
  if (threadIdx.x < 32) sidx[threadIdx.x] = g_idx[chain][b][threadIdx.x];
  else if (threadIdx.x < 32 + A_DIM) sact[threadIdx.x - 32] = act_t[b * A_DIM + (threadIdx.x - 32)];
  __syncthreads();

  float4 acc = make_float4(0.f, 0.f, 0.f, 0.f);
#pragma unroll 4
  for (int s = 0; s < 32; s++) {
    int id = sidx[s];
    if (id >= 0) {
      float4 w = *reinterpret_cast<const float4*>(w_pre + (size_t)(s * 32 + id) * HDIM + col);
      acc.x += w.x; acc.y += w.y; acc.z += w.z; acc.w += w.w;
    }
  }
#pragma unroll
  for (int j = 0; j < A_DIM; j++) {
    float a = sact[j];
    float4 w = *reinterpret_cast<const float4*>(w_pre + (size_t)(1024 + j) * HDIM + col);
    acc.x = fmaf(a, w.x, acc.x); acc.y = fmaf(a, w.y, acc.y);
    acc.z = fmaf(a, w.z, acc.z); acc.w = fmaf(a, w.w, acc.w);
  }
  float4 bb = *reinterpret_cast<const float4*>(b_pre + col);
  acc.x += bb.x; acc.y += bb.y; acc.z += bb.z; acc.w += bb.w;
  acc.x = (acc.x > 0.f) ? acc.x : expm1f(acc.x);
  acc.y = (acc.y > 0.f) ? acc.y : expm1f(acc.y);
  acc.z = (acc.z > 0.f) ? acc.z : expm1f(acc.z);
  acc.w = (acc.w > 0.f) ? acc.w : expm1f(acc.w);
  *reinterpret_cast<float4*>(&g_x[chain][b][col]) = acc;
}

// ---------------- generic fp32 GEMM: C = act([A1|A2] @ W + b) ----------------
// tiles: 64(M) x 64(N), BK=32, 128 threads, 8x4 outputs per thread.
// Register-prefetch double buffering, one barrier per k-tile.
#define BM 64
#define BN 64
#define BKK 32
#define TM 8
#define TN 4

struct GArg {
  const float* A1;
  const float* A2;
  const float* W;
  const float* bias;
  float* C;
  int k1;   // width of A1 part
  int K;    // total K
};
struct GemmParams {
  GArg a[4];
  int N;       // output width (also W row stride and C row stride)
  int lda1;
  int lda2;
  int act;     // 1: elu
};

struct Frag { float4 a[4]; float4 w[4]; };

__device__ __forceinline__ void load_frag(Frag& f, const GArg& g, const GemmParams& p,
                                          int row0, int col0, int kb, int tid) {
  const int K = g.K, k1 = g.k1;
  const bool a1vec = (kb + BKK <= k1);
  const bool a2vec = (kb >= k1) && (kb + BKK <= K) && (g.A2 != nullptr);
  if (a1vec || a2vec) {
    const float* Abase = a1vec ? g.A1 : g.A2;
    const int lda = a1vec ? p.lda1 : p.lda2;
    const int koff = a1vec ? kb : (kb - k1);
#pragma unroll
    for (int l = 0; l < 4; l++) {
      int vidx = tid + l * 128;           // 0..511
      int ar = vidx >> 3;                 // 0..63
      int ac4 = (vidx & 7) << 2;          // 0,4,...,28
      f.a[l] = *reinterpret_cast<const float4*>(
          Abase + (size_t)(row0 + ar) * lda + koff + ac4);
    }
  } else {
#pragma unroll
    for (int l = 0; l < 4; l++) {
      int vidx = tid + l * 128;
      int ar = vidx >> 3;
      int ac4 = (vidx & 7) << 2;
      float tmp[4];
#pragma unroll
      for (int c = 0; c < 4; c++) {
        int gc = kb + ac4 + c;
        float v = 0.f;
        if (gc < K) {
          int gr = row0 + ar;
          if (gc < k1) v = g.A1[(size_t)gr * p.lda1 + gc];
          else         v = g.A2[(size_t)gr * p.lda2 + (gc - k1)];
        }
        tmp[c] = v;
      }
      f.a[l] = make_float4(tmp[0], tmp[1], tmp[2], tmp[3]);
    }
  }

  if (kb + BKK <= K) {
#pragma unroll
    for (int l = 0; l < 4; l++) {
      int vidx = tid + l * 128;           // 0..511
      int wr = vidx >> 4;                 // 0..31
      int wc4 = (vidx & 15) << 2;         // 0,4,...,60
      f.w[l] = *reinterpret_cast<const float4*>(
          g.W + (size_t)(kb + wr) * p.N + col0 + wc4);
    }
  } else {
#pragma unroll
    for (int l = 0; l < 4; l++) {
      int vidx = tid + l * 128;
      int wr = vidx >> 4;
      int wc4 = (vidx & 15) << 2;
      int gk = kb + wr;
      if (gk < K) {
        f.w[l] = *reinterpret_cast<const float4*>(
            g.W + (size_t)gk * p.N + col0 + wc4);
      } else {
        f.w[l] = make_float4(0.f, 0.f, 0.f, 0.f);
      }
    }
  }
}

__global__ __launch_bounds__(128) void gemm_k(GemmParams p) {
  const GArg g = p.a[blockIdx.z];
  const int K = g.K;
  __shared__ float As[2][BKK][BM + 4];
  __shared__ float Ws[2][BKK][BN];
  const int tid = threadIdx.x;
  const int tx = tid & 15;          // N direction (16 * TN = 64)
  const int ty = tid >> 4;          // M direction (8 * TM = 64)
  const int row0 = blockIdx.y * BM;
  const int col0 = blockIdx.x * BN;

  float acc[TM][TN];
#pragma unroll
  for (int i = 0; i < TM; i++)
#pragma unroll
    for (int j = 0; j < TN; j++) acc[i][j] = 0.f;

  const int ktiles = (K + BKK - 1) / BKK;
  Frag f;
  load_frag(f, g, p, row0, col0, 0, tid);

  for (int kt = 0; kt < ktiles; kt++) {
    const int buf = kt & 1;
#pragma unroll
    for (int l = 0; l < 4; l++) {
      int vidx = tid + l * 128;
      int ar = vidx >> 3;
      int ac4 = (vidx & 7) << 2;
      As[buf][ac4 + 0][ar] = f.a[l].x;
      As[buf][ac4 + 1][ar] = f.a[l].y;
      As[buf][ac4 + 2][ar] = f.a[l].z;
      As[buf][ac4 + 3][ar] = f.a[l].w;
    }
#pragma unroll
    for (int l = 0; l < 4; l++) {
      int vidx = tid + l * 128;
      int wr = vidx >> 4;
      int wc4 = (vidx & 15) << 2;
      *reinterpret_cast<float4*>(&Ws[buf][wr][wc4]) = f.w[l];
    }
    __syncthreads();

    if (kt + 1 < ktiles) load_frag(f, g, p, row0, col0, (kt + 1) * BKK, tid);

#pragma unroll
    for (int kk = 0; kk < BKK; kk++) {
      float a[TM], b[TN];
#pragma unroll
      for (int i = 0; i < TM; i++) a[i] = As[buf][kk][ty * TM + i];
#pragma unroll
      for (int j = 0; j < TN; j++) b[j] = Ws[buf][kk][tx * TN + j];
#pragma unroll
      for (int i = 0; i < TM; i++)
#pragma unroll
        for (int j = 0; j < TN; j++) acc[i][j] = fmaf(a[i], b[j], acc[i][j]);
    }
    // next iteration writes the OTHER buffer, whose previous readers all
    // passed the barrier above -> safe with a single barrier per tile.
  }

#pragma unroll
  for (int i = 0; i < TM; i++) {
    int r = row0 + ty * TM + i;
    int c = col0 + tx * TN;
    float4 v;
    v.x = acc[i][0] + g.bias[c + 0];
    v.y = acc[i][1] + g.bias[c + 1];
    v.z = acc[i][2] + g.bias[c + 2];
    v.w = acc[i][3] + g.bias[c + 3];
    if (p.act) {
      v.x = (v.x > 0.f) ? v.x : expm1f(v.x);
      v.y = (v.y > 0.f) ? v.y : expm1f(v.y);
      v.z = (v.z > 0.f) ? v.z : expm1f(v.z);
      v.w = (v.w > 0.f) ? v.w : expm1f(v.w);
    }
    *reinterpret_cast<float4*>(&g.C[(size_t)r * p.N + c]) = v;
  }
}

// ---------------- GRU gate kernel: LN over 3072 + gates -> new deter ----------------
// Single global read: each thread caches its 12 floats (float4 of each third)
// in registers, reduces mean/var via shuffles, computes gates from registers.
__global__ __launch_bounds__(256) void gate_k(const float* __restrict__ ln_scale,
                                              const float* __restrict__ ln_offset,
                                              float* __restrict__ postf,
                                              float* __restrict__ priorf,
                                              int t) {
  const int row = blockIdx.x;            // 0..511
  const int chain = row >> 7, b = row & 127;
  const float* gg = g_g[chain][b];
  const int tid = threadIdx.x;
  const int lane = tid & 31, wid = tid >> 5;
  const int col = tid * 4;               // 0..1020
  __shared__ float red[8];

  const float4 vr = *reinterpret_cast<const float4*>(gg + col);
  const float4 vc = *reinterpret_cast<const float4*>(gg + 1024 + col);
  const float4 vu = *reinterpret_cast<const float4*>(gg + 2048 + col);

  // mean
  float s = (vr.x + vr.y + vr.z + vr.w)
          + (vc.x + vc.y + vc.z + vc.w)
          + (vu.x + vu.y + vu.z + vu.w);
#pragma unroll
  for (int o = 16; o; o >>= 1) s += __shfl_down_sync(0xffffffffu, s, o);
  if (lane == 0) red[wid] = s;
  __syncthreads();
  if (tid == 0) {
    float acc = 0.f;
#pragma unroll
    for (int w = 0; w < 8; w++) acc += red[w];
    red[0] = acc;
  }
  __syncthreads();
  const float mean = red[0] * (1.0f / 3072.0f);
  __syncthreads();

  // variance (mean-centered, matches jnp.var)
  float vs = 0.f;
  {
    float d;
    d = vr.x - mean; vs += d * d;  d = vr.y - mean; vs += d * d;
    d = vr.z - mean; vs += d * d;  d = vr.w - mean; vs += d * d;
    d = vc.x - mean; vs += d * d;  d = vc.y - mean; vs += d * d;
    d = vc.z - mean; vs += d * d;  d = vc.w - mean; vs += d * d;
    d = vu.x - mean; vs += d * d;  d = vu.y - mean; vs += d * d;
    d = vu.z - mean; vs += d * d;  d = vu.w - mean; vs += d * d;
  }
#pragma unroll
  for (int o = 16; o; o >>= 1) vs += __shfl_down_sync(0xffffffffu, vs, o);
  if (lane == 0) red[wid] = vs;
  __syncthreads();
  if (tid == 0) {
    float acc = 0.f;
#pragma unroll
    for (int w = 0; w < 8; w++) acc += red[w];
    red[0] = acc;
  }
  __syncthreads();
  const float var = red[0] * (1.0f / 3072.0f);
  const float rs = 1.0f / sqrtf(var + 1e-5f);

  const float4 sr = *reinterpret_cast<const float4*>(ln_scale + col);
  const float4 sc = *reinterpret_cast<const float4*>(ln_scale + 1024 + col);
  const float4 su = *reinterpret_cast<const float4*>(ln_scale + 2048 + col);
  const float4 or_ = *reinterpret_cast<const float4*>(ln_offset + col);
  const float4 oc = *reinterpret_cast<const float4*>(ln_offset + 1024 + col);
  const float4 ou = *reinterpret_cast<const float4*>(ln_offset + 2048 + col);
  const float4 h4 = *reinterpret_cast<const float4*>(&g_deter[chain][b][col]);

  float4 nd4;
  {
    const float gr[4] = {vr.x, vr.y, vr.z, vr.w};
    const float gc[4] = {vc.x, vc.y, vc.z, vc.w};
    const float gu[4] = {vu.x, vu.y, vu.z, vu.w};
    const float ssr[4] = {sr.x, sr.y, sr.z, sr.w};
    const float ssc[4] = {sc.x, sc.y, sc.z, sc.w};
    const float ssu[4] = {su.x, su.y, su.z, su.w};
    const float oor[4] = {or_.x, or_.y, or_.z, or_.w};
    const float ooc[4] = {oc.x, oc.y, oc.z, oc.w};
    const float oou[4] = {ou.x, ou.y, ou.z, ou.w};
    const float hh[4] = {h4.x, h4.y, h4.z, h4.w};
    float nd[4];
#pragma unroll
    for (int k = 0; k < 4; k++) {
      float pr = (gr[k] - mean) * rs * ssr[k] + oor[k];
      float pc = (gc[k] - mean) * rs * ssc[k] + ooc[k];
      float pu = (gu[k] - mean) * rs * ssu[k] + oou[k];
      float r = 1.0f / (1.0f + expf(-pr));
      float c = tanhf(r * pc);
      float u = 1.0f / (1.0f + expf(-(pu - 1.0f)));
      nd[k] = u * c + (1.0f - u) * hh[k];
    }
    nd4 = make_float4(nd[0], nd[1], nd[2], nd[3]);
  }
  *reinterpret_cast<float4*>(&g_deter[chain][b][col]) = nd4;
  if (chain == 2)
    *reinterpret_cast<float4*>(&postf [((size_t)t * BATCH + b) * 2048 + col]) = nd4;
  else if (chain == 3)
    *reinterpret_cast<float4*>(&priorf[((size_t)t * BATCH + b) * 2048 + col]) = nd4;
}

// ---------------- sample kernel: threefry + gumbel argmax -> idx (+ one-hot feats) ----
__global__ __launch_bounds__(128) void sample_k(const float* __restrict__ st0,
                                                const float* __restrict__ st1,
                                                float* __restrict__ postf,
                                                float* __restrict__ priorf,
                                                int t) {
  const int warp = blockIdx.x * 4 + (threadIdx.x >> 5);  // 0..16383
  const int lane = threadIdx.x & 31;
  const int chain = warp >> 12;
  const int bs = warp & 4095;
  const int b = bs >> 5, s = bs & 31;

  // fold offsets: prior t, post k2=t+2T=+128, post_feat k2=t+4T=+256, prior_feat t+5T=+320
  int tt = t + (chain == 0 ? 0 : chain == 1 ? 128 : chain == 2 ? 256 : 320);
  unsigned fk0, fk1;
  tf2x32(0u, 7u, 0u, (unsigned)tt, fk0, fk1);

  const unsigned i = (unsigned)(b * 1024 + s * 32 + lane);  // flat (B,S,D)
  unsigned bits;
#if JAX_PARTITIONABLE
  { unsigned o0, o1; tf2x32(fk0, fk1, 0u, i, o0, o1); bits = o0 ^ o1; }
#else
  { unsigned j = (i < 65536u) ? i : (i - 65536u);
    unsigned o0, o1; tf2x32(fk0, fk1, j, j + 65536u, o0, o1);
    bits = (i < 65536u) ? o0 : o1; }
#endif
  float u = __uint_as_float((bits >> 9) | 0x3f800000u) - 1.0f;
  if (u == 0.0f) u = 1.17549435e-38f;   // jnp.finfo(f32).tiny
  float gmb = -logf(-logf(u));

  const float* st = (chain == 0) ? st0 : (chain == 1) ? st1 : &g_stats[chain][0][0];
  float val = st[i] + gmb;

  // warp argmax with lowest-index tie-break (jnp.argmax semantics)
  float bv = val; int bi = lane;
#pragma unroll
  for (int off = 16; off; off >>= 1) {
    float ov = __shfl_down_sync(0xffffffffu, bv, off);
    int   oi = __shfl_down_sync(0xffffffffu, bi, off);
    if (ov > bv || (ov == bv && oi < bi)) { bv = ov; bi = oi; }
  }
  bi = __shfl_sync(0xffffffffu, bi, 0);

  if (lane == 0) g_idx[chain][b][s] = bi;
  if (chain >= 2) {
    float oh = (lane == bi) ? 1.0f : 0.0f;
    float* dst = (chain == 2) ? postf : priorf;
    dst[((size_t)t * BATCH + b) * 2048 + 1024 + s * 32 + lane] = oh;
  }
}

// ---------------- init: zero recurrent state, idx sentinel ----------------
__global__ void init_k() {
  size_t n = (size_t)NCHAIN * BATCH * HDIM;
  size_t idx = (size_t)blockIdx.x * blockDim.x + threadIdx.x;
  if (idx < n) (&g_deter[0][0][0])[idx] = 0.f;
  if (idx < (size_t)NCHAIN * BATCH * 32) (&g_idx[0][0][0])[idx] = -1;
}

// ---------------- host orchestration ----------------
extern "C" void kernel_launch(void* const* d_in, const int* in_sizes, int n_in,
                              void* d_out, int out_size) {
  (void)in_sizes; (void)n_in; (void)out_size;
  const float* embeds   = (const float*)d_in[0];
  const float* actions  = (const float*)d_in[1];
  const float* w_pre    = (const float*)d_in[2];
  const float* b_pre    = (const float*)d_in[3];
  const float* w_gru    = (const float*)d_in[4];
  const float* b_gru    = (const float*)d_in[5];
  const float* ln_scale = (const float*)d_in[6];
  const float* ln_offset= (const float*)d_in[7];
  const float* w_prior1 = (const float*)d_in[8];
  const float* b_prior1 = (const float*)d_in[9];
  const float* w_prior2 = (const float*)d_in[10];
  const float* b_prior2 = (const float*)d_in[11];
  const float* w_post1  = (const float*)d_in[12];
  const float* b_post1  = (const float*)d_in[13];
  const float* w_post2  = (const float*)d_in[14];
  const float* b_post2  = (const float*)d_in[15];

  float* out    = (float*)d_out;
  float* priors = out;
  float* posts  = priors + (size_t)T_STEPS * BATCH * 1024;
  float* postf  = posts  + (size_t)T_STEPS * BATCH * 1024;
  float* priorf = postf  + (size_t)T_STEPS * BATCH * 2048;

  float *p_deter, *p_x, *p_g, *p_h1, *p_stats;
  cudaGetSymbolAddress((void**)&p_deter, g_deter);
  cudaGetSymbolAddress((void**)&p_x,     g_x);
  cudaGetSymbolAddress((void**)&p_g,     g_g);
  cudaGetSymbolAddress((void**)&p_h1,    g_h1);
  cudaGetSymbolAddress((void**)&p_stats, g_stats);

  init_k<<<(NCHAIN * BATCH * HDIM + 255) / 256, 256>>>();

  for (int t = 0; t < T_STEPS; t++) {
    // ---- pre: x = elu([stoch | act_t] @ w_pre + b_pre) via one-hot gather
    pre_k<<<NCHAIN * BATCH, 256>>>(actions + (size_t)t * BATCH * A_DIM, w_pre, b_pre);

    // ---- gru linear: g = [x | deter] @ w_gru + b_gru, M=512, K=2048, N=3072
    {
      GemmParams p = {};
      p.a[0].A1 = p_x; p.a[0].A2 = p_deter;
      p.a[0].W = w_gru; p.a[0].bias = b_gru; p.a[0].C = p_g;
      p.a[0].k1 = 1024; p.a[0].K = 2048;
      p.N = 3072; p.lda1 = 1024; p.lda2 = 1024; p.act = 0;
      gemm_k<<<dim3(3072 / BN, 512 / BM, 1), 128>>>(p);
    }
    // ---- LN + gates -> deter (and nd -> features for chains 2,3)
    gate_k<<<NCHAIN * BATCH, 256>>>(ln_scale, ln_offset, postf, priorf, t);

    // ---- stats layer 1 (per chain): prior chains K=1024, post chains K=2048
    {
      GemmParams p = {};
      for (int c = 0; c < 4; c++) {
        p.a[c].A1 = p_deter + (size_t)c * BATCH * HDIM;
        p.a[c].C  = p_h1    + (size_t)c * BATCH * HDIM;
        if (c == 0 || c == 3) {  // prior chains
          p.a[c].A2 = nullptr; p.a[c].k1 = 1024; p.a[c].K = 1024;
          p.a[c].W = w_prior1; p.a[c].bias = b_prior1;
        } else {                 // post chains: [deter | emb_t]
          p.a[c].A2 = embeds + (size_t)t * BATCH * EMBED;
          p.a[c].k1 = 1024; p.a[c].K = 2048;
          p.a[c].W = w_post1; p.a[c].bias = b_post1;
        }
      }
      p.N = 1024; p.lda1 = 1024; p.lda2 = 1024; p.act = 1;
      gemm_k<<<dim3(1024 / BN, BATCH / BM, 4), 128>>>(p);
    }
    // ---- stats layer 2 (per chain): stats = h1 @ w2 + b2
    {
      GemmParams p = {};
      for (int c = 0; c < 4; c++) {
        p.a[c].A1 = p_h1 + (size_t)c * BATCH * HDIM;
        p.a[c].A2 = nullptr; p.a[c].k1 = 1024; p.a[c].K = 1024;
        if (c == 0 || c == 3) { p.a[c].W = w_prior2; p.a[c].bias = b_prior2; }
        else                  { p.a[c].W = w_post2;  p.a[c].bias = b_post2;  }
      }
      p.a[0].C = priors + (size_t)t * BATCH * 1024;
      p.a[1].C = posts  + (size_t)t * BATCH * 1024;
      p.a[2].C = p_stats + (size_t)2 * BATCH * DIST;
      p.a[3].C = p_stats + (size_t)3 * BATCH * DIST;
      p.N = 1024; p.lda1 = 1024; p.lda2 = 1024; p.act = 0;
      gemm_k<<<dim3(1024 / BN, BATCH / BM, 4), 128>>>(p);
    }
    // ---- sample: threefry gumbel argmax -> idx (+ one-hot features)
    sample_k<<<4096, 128>>>(priors + (size_t)t * BATCH * 1024,
                            posts  + (size_t)t * BATCH * 1024,
                            postf, priorf, t);
  }
}

// round 7
// speedup vs baseline: 1.1347x; 1.1347x over previous
#include <cuda_runtime.h>
#include <math.h>
#include <stdint.h>

// ---------------- problem constants ----------------
#define T_STEPS 64
#define BATCH   128
#define A_DIM   6
#define EMBED   1024
#define HDIM    1024
#define G3      3072
#define DIST    1024
#define NCHAIN  4
#define JAX_PARTITIONABLE 1   // validated R5: rel_err 2.2e-6

typedef unsigned long long ull;

// ---------------- packed f32x2 helpers (sm_103a FFMA2 path) ----------------
__device__ __forceinline__ ull pack2(float lo, float hi) {
  ull r;
  asm("mov.b64 %0, {%1, %2};" : "=l"(r) : "f"(lo), "f"(hi));
  return r;
}
__device__ __forceinline__ void ffma2(ull& d, ull a, ull b) {
  asm("fma.rn.f32x2 %0, %1, %2, %3;" : "=l"(d) : "l"(a), "l"(b), "l"(d));
}
__device__ __forceinline__ void unpack2(ull v, float& lo, float& hi) {
  asm("mov.b64 {%0, %1}, %2;" : "=f"(lo), "=f"(hi) : "l"(v));
}

// ---------------- device scratch (static: no allocation) ----------------
__device__ int   g_idx  [NCHAIN][BATCH][32];   // argmax index per (chain,b,group); -1 = zero state
__device__ float g_deter[NCHAIN][BATCH][HDIM];
__device__ float g_x    [NCHAIN][BATCH][HDIM];
__device__ float g_g    [NCHAIN][BATCH][G3];
__device__ float g_h1   [NCHAIN][BATCH][HDIM];
__device__ float g_stats[NCHAIN][BATCH][DIST];   // only chains 2,3 read back

// ---------------- threefry2x32 (exact JAX semantics) ----------------
__device__ __forceinline__ void tf2x32(unsigned k0, unsigned k1, unsigned x0, unsigned x1,
                                       unsigned& o0, unsigned& o1) {
  unsigned k2 = k0 ^ k1 ^ 0x1BD11BDAu;
  x0 += k0; x1 += k1;
#define TF_RND(r) { x0 += x1; x1 = (x1 << (r)) | (x1 >> (32 - (r))); x1 ^= x0; }
  TF_RND(13) TF_RND(15) TF_RND(26) TF_RND(6)
  x0 += k1; x1 += k2 + 1u;
  TF_RND(17) TF_RND(29) TF_RND(16) TF_RND(24)
  x0 += k2; x1 += k0 + 2u;
  TF_RND(13) TF_RND(15) TF_RND(26) TF_RND(6)
  x0 += k0; x1 += k1 + 3u;
  TF_RND(17) TF_RND(29) TF_RND(16) TF_RND(24)
  x0 += k1; x1 += k2 + 4u;
  TF_RND(13) TF_RND(15) TF_RND(26) TF_RND(6)
  x0 += k2; x1 += k0 + 5u;
#undef TF_RND
  o0 = x0; o1 = x1;
}

// ---------------- pre layer: x = elu(gather(w_pre, idx) + act @ w_pre[1024:] + b_pre) ----
__global__ __launch_bounds__(256) void pre_k(const float* __restrict__ act_t,
                                             const float* __restrict__ w_pre,
                                             const float* __restrict__ b_pre) {
  const int row = blockIdx.x;            // 0..511
  const int chain = row >> 7, b = row & 127;
  const int col = threadIdx.x * 4;       // 256 threads * 4 = 1024 cols

  __shared__ int   sidx[32];
  __shared__ float sact[A_DIM];
  if (threadIdx.x < 32) sidx[threadIdx.x] = g_idx[chain][b][threadIdx.x];
  else if (threadIdx.x < 32 + A_DIM) sact[threadIdx.x - 32] = act_t[b * A_DIM + (threadIdx.x - 32)];
  __syncthreads();

  float4 acc = make_float4(0.f, 0.f, 0.f, 0.f);
#pragma unroll 4
  for (int s = 0; s < 32; s++) {
    int id = sidx[s];
    if (id >= 0) {
      float4 w = *reinterpret_cast<const float4*>(w_pre + (size_t)(s * 32 + id) * HDIM + col);
      acc.x += w.x; acc.y += w.y; acc.z += w.z; acc.w += w.w;
    }
  }
#pragma unroll
  for (int j = 0; j < A_DIM; j++) {
    float a = sact[j];
    float4 w = *reinterpret_cast<const float4*>(w_pre + (size_t)(1024 + j) * HDIM + col);
    acc.x = fmaf(a, w.x, acc.x); acc.y = fmaf(a, w.y, acc.y);
    acc.z = fmaf(a, w.z, acc.z); acc.w = fmaf(a, w.w, acc.w);
  }
  float4 bb = *reinterpret_cast<const float4*>(b_pre + col);
  acc.x += bb.x; acc.y += bb.y; acc.z += bb.z; acc.w += bb.w;
  acc.x = (acc.x > 0.f) ? acc.x : expm1f(acc.x);
  acc.y = (acc.y > 0.f) ? acc.y : expm1f(acc.y);
  acc.z = (acc.z > 0.f) ? acc.z : expm1f(acc.z);
  acc.w = (acc.w > 0.f) ? acc.w : expm1f(acc.w);
  *reinterpret_cast<float4*>(&g_x[chain][b][col]) = acc;
}

// ---------------- generic fp32 GEMM with packed FFMA2 inner loop ----------------
// tiles: 64(M) x 64(N), BK=32, 128 threads, 8x4 outputs per thread (as 4 M-pairs).
// Register-prefetch double buffering, one barrier per k-tile.
// Accumulation per output element is the same fma.rn chain in the same k-order
// as the scalar version -> bit-identical results.
#define BM 64
#define BN 64
#define BKK 32
#define TM 8
#define TN 4

struct GArg {
  const float* A1;
  const float* A2;
  const float* W;
  const float* bias;
  float* C;
  int k1;   // width of A1 part
  int K;    // total K
};
struct GemmParams {
  GArg a[4];
  int N;       // output width (also W row stride and C row stride)
  int lda1;
  int lda2;
  int act;     // 1: elu
};

struct Frag { float4 a[4]; float4 w[4]; };

__device__ __forceinline__ void load_frag(Frag& f, const GArg& g, const GemmParams& p,
                                          int row0, int col0, int kb, int tid) {
  const int K = g.K, k1 = g.k1;
  const bool a1vec = (kb + BKK <= k1);
  const bool a2vec = (kb >= k1) && (kb + BKK <= K) && (g.A2 != nullptr);
  if (a1vec || a2vec) {
    const float* Abase = a1vec ? g.A1 : g.A2;
    const int lda = a1vec ? p.lda1 : p.lda2;
    const int koff = a1vec ? kb : (kb - k1);
#pragma unroll
    for (int l = 0; l < 4; l++) {
      int vidx = tid + l * 128;           // 0..511
      int ar = vidx >> 3;                 // 0..63
      int ac4 = (vidx & 7) << 2;          // 0,4,...,28
      f.a[l] = *reinterpret_cast<const float4*>(
          Abase + (size_t)(row0 + ar) * lda + koff + ac4);
    }
  } else {
#pragma unroll
    for (int l = 0; l < 4; l++) {
      int vidx = tid + l * 128;
      int ar = vidx >> 3;
      int ac4 = (vidx & 7) << 2;
      float tmp[4];
#pragma unroll
      for (int c = 0; c < 4; c++) {
        int gc = kb + ac4 + c;
        float v = 0.f;
        if (gc < K) {
          int gr = row0 + ar;
          if (gc < k1) v = g.A1[(size_t)gr * p.lda1 + gc];
          else         v = g.A2[(size_t)gr * p.lda2 + (gc - k1)];
        }
        tmp[c] = v;
      }
      f.a[l] = make_float4(tmp[0], tmp[1], tmp[2], tmp[3]);
    }
  }

  if (kb + BKK <= K) {
#pragma unroll
    for (int l = 0; l < 4; l++) {
      int vidx = tid + l * 128;           // 0..511
      int wr = vidx >> 4;                 // 0..31
      int wc4 = (vidx & 15) << 2;         // 0,4,...,60
      f.w[l] = *reinterpret_cast<const float4*>(
          g.W + (size_t)(kb + wr) * p.N + col0 + wc4);
    }
  } else {
#pragma unroll
    for (int l = 0; l < 4; l++) {
      int vidx = tid + l * 128;
      int wr = vidx >> 4;
      int wc4 = (vidx & 15) << 2;
      int gk = kb + wr;
      if (gk < K) {
        f.w[l] = *reinterpret_cast<const float4*>(
            g.W + (size_t)gk * p.N + col0 + wc4);
      } else {
        f.w[l] = make_float4(0.f, 0.f, 0.f, 0.f);
      }
    }
  }
}

__global__ __launch_bounds__(128) void gemm_k(GemmParams p) {
  const GArg g = p.a[blockIdx.z];
  const int K = g.K;
  // row stride BM+4=68 floats = 272B (8B-aligned) -> LDS.64 of M-pairs is legal
  __shared__ float As[2][BKK][BM + 4];
  __shared__ float Ws[2][BKK][BN];
  const int tid = threadIdx.x;
  const int tx = tid & 15;          // N direction (16 * TN = 64)
  const int ty = tid >> 4;          // M direction (8 * TM = 64)
  const int row0 = blockIdx.y * BM;
  const int col0 = blockIdx.x * BN;

  // packed accumulators: acc2[i2][j] = {C[row 2*i2][j], C[row 2*i2+1][j]}
  ull acc2[TM / 2][TN];
#pragma unroll
  for (int i = 0; i < TM / 2; i++)
#pragma unroll
    for (int j = 0; j < TN; j++) acc2[i][j] = 0ull;

  const int ktiles = (K + BKK - 1) / BKK;
  Frag f;
  load_frag(f, g, p, row0, col0, 0, tid);

  for (int kt = 0; kt < ktiles; kt++) {
    const int buf = kt & 1;
#pragma unroll
    for (int l = 0; l < 4; l++) {
      int vidx = tid + l * 128;
      int ar = vidx >> 3;
      int ac4 = (vidx & 7) << 2;
      As[buf][ac4 + 0][ar] = f.a[l].x;
      As[buf][ac4 + 1][ar] = f.a[l].y;
      As[buf][ac4 + 2][ar] = f.a[l].z;
      As[buf][ac4 + 3][ar] = f.a[l].w;
    }
#pragma unroll
    for (int l = 0; l < 4; l++) {
      int vidx = tid + l * 128;
      int wr = vidx >> 4;
      int wc4 = (vidx & 15) << 2;
      *reinterpret_cast<float4*>(&Ws[buf][wr][wc4]) = f.w[l];
    }
    __syncthreads();

    if (kt + 1 < ktiles) load_frag(f, g, p, row0, col0, (kt + 1) * BKK, tid);

#pragma unroll
    for (int kk = 0; kk < BKK; kk++) {
      // A pairs: direct 8-byte shared loads (broadcast within half-warp)
      const ull* arow = reinterpret_cast<const ull*>(&As[buf][kk][ty * TM]);
      ull a2[TM / 2];
#pragma unroll
      for (int i = 0; i < TM / 2; i++) a2[i] = arow[i];
      // B values: one 16B shared load, splat each into both halves
      float4 bv = *reinterpret_cast<const float4*>(&Ws[buf][kk][tx * TN]);
      ull b2[TN];
      b2[0] = pack2(bv.x, bv.x);
      b2[1] = pack2(bv.y, bv.y);
      b2[2] = pack2(bv.z, bv.z);
      b2[3] = pack2(bv.w, bv.w);
#pragma unroll
      for (int i = 0; i < TM / 2; i++)
#pragma unroll
        for (int j = 0; j < TN; j++) ffma2(acc2[i][j], a2[i], b2[j]);
    }
    // next iteration writes the OTHER buffer; single barrier per tile is safe.
  }

#pragma unroll
  for (int i2 = 0; i2 < TM / 2; i2++) {
    float lo[TN], hi[TN];
#pragma unroll
    for (int j = 0; j < TN; j++) unpack2(acc2[i2][j], lo[j], hi[j]);
#pragma unroll
    for (int h = 0; h < 2; h++) {
      const float* av = h ? hi : lo;
      int r = row0 + ty * TM + 2 * i2 + h;
      int c = col0 + tx * TN;
      float4 v;
      v.x = av[0] + g.bias[c + 0];
      v.y = av[1] + g.bias[c + 1];
      v.z = av[2] + g.bias[c + 2];
      v.w = av[3] + g.bias[c + 3];
      if (p.act) {
        v.x = (v.x > 0.f) ? v.x : expm1f(v.x);
        v.y = (v.y > 0.f) ? v.y : expm1f(v.y);
        v.z = (v.z > 0.f) ? v.z : expm1f(v.z);
        v.w = (v.w > 0.f) ? v.w : expm1f(v.w);
      }
      *reinterpret_cast<float4*>(&g.C[(size_t)r * p.N + c]) = v;
    }
  }
}

// ---------------- GRU gate kernel: LN over 3072 + gates -> new deter ----------------
__global__ __launch_bounds__(256) void gate_k(const float* __restrict__ ln_scale,
                                              const float* __restrict__ ln_offset,
                                              float* __restrict__ postf,
                                              float* __restrict__ priorf,
                                              int t) {
  const int row = blockIdx.x;            // 0..511
  const int chain = row >> 7, b = row & 127;
  const float* gg = g_g[chain][b];
  const int tid = threadIdx.x;
  const int lane = tid & 31, wid = tid >> 5;
  const int col = tid * 4;               // 0..1020
  __shared__ float red[8];

  const float4 vr = *reinterpret_cast<const float4*>(gg + col);
  const float4 vc = *reinterpret_cast<const float4*>(gg + 1024 + col);
  const float4 vu = *reinterpret_cast<const float4*>(gg + 2048 + col);

  float s = (vr.x + vr.y + vr.z + vr.w)
          + (vc.x + vc.y + vc.z + vc.w)
          + (vu.x + vu.y + vu.z + vu.w);
#pragma unroll
  for (int o = 16; o; o >>= 1) s += __shfl_down_sync(0xffffffffu, s, o);
  if (lane == 0) red[wid] = s;
  __syncthreads();
  if (tid == 0) {
    float acc = 0.f;
#pragma unroll
    for (int w = 0; w < 8; w++) acc += red[w];
    red[0] = acc;
  }
  __syncthreads();
  const float mean = red[0] * (1.0f / 3072.0f);
  __syncthreads();

  float vs = 0.f;
  {
    float d;
    d = vr.x - mean; vs += d * d;  d = vr.y - mean; vs += d * d;
    d = vr.z - mean; vs += d * d;  d = vr.w - mean; vs += d * d;
    d = vc.x - mean; vs += d * d;  d = vc.y - mean; vs += d * d;
    d = vc.z - mean; vs += d * d;  d = vc.w - mean; vs += d * d;
    d = vu.x - mean; vs += d * d;  d = vu.y - mean; vs += d * d;
    d = vu.z - mean; vs += d * d;  d = vu.w - mean; vs += d * d;
  }
#pragma unroll
  for (int o = 16; o; o >>= 1) vs += __shfl_down_sync(0xffffffffu, vs, o);
  if (lane == 0) red[wid] = vs;
  __syncthreads();
  if (tid == 0) {
    float acc = 0.f;
#pragma unroll
    for (int w = 0; w < 8; w++) acc += red[w];
    red[0] = acc;
  }
  __syncthreads();
  const float var = red[0] * (1.0f / 3072.0f);
  const float rs = 1.0f / sqrtf(var + 1e-5f);

  const float4 sr = *reinterpret_cast<const float4*>(ln_scale + col);
  const float4 sc = *reinterpret_cast<const float4*>(ln_scale + 1024 + col);
  const float4 su = *reinterpret_cast<const float4*>(ln_scale + 2048 + col);
  const float4 or_ = *reinterpret_cast<const float4*>(ln_offset + col);
  const float4 oc = *reinterpret_cast<const float4*>(ln_offset + 1024 + col);
  const float4 ou = *reinterpret_cast<const float4*>(ln_offset + 2048 + col);
  const float4 h4 = *reinterpret_cast<const float4*>(&g_deter[chain][b][col]);

  float4 nd4;
  {
    const float gr[4] = {vr.x, vr.y, vr.z, vr.w};
    const float gc[4] = {vc.x, vc.y, vc.z, vc.w};
    const float gu[4] = {vu.x, vu.y, vu.z, vu.w};
    const float ssr[4] = {sr.x, sr.y, sr.z, sr.w};
    const float ssc[4] = {sc.x, sc.y, sc.z, sc.w};
    const float ssu[4] = {su.x, su.y, su.z, su.w};
    const float oor[4] = {or_.x, or_.y, or_.z, or_.w};
    const float ooc[4] = {oc.x, oc.y, oc.z, oc.w};
    const float oou[4] = {ou.x, ou.y, ou.z, ou.w};
    const float hh[4] = {h4.x, h4.y, h4.z, h4.w};
    float nd[4];
#pragma unroll
    for (int k = 0; k < 4; k++) {
      float pr = (gr[k] - mean) * rs * ssr[k] + oor[k];
      float pc = (gc[k] - mean) * rs * ssc[k] + ooc[k];
      float pu = (gu[k] - mean) * rs * ssu[k] + oou[k];
      float r = 1.0f / (1.0f + expf(-pr));
      float c = tanhf(r * pc);
      float u = 1.0f / (1.0f + expf(-(pu - 1.0f)));
      nd[k] = u * c + (1.0f - u) * hh[k];
    }
    nd4 = make_float4(nd[0], nd[1], nd[2], nd[3]);
  }
  *reinterpret_cast<float4*>(&g_deter[chain][b][col]) = nd4;
  if (chain == 2)
    *reinterpret_cast<float4*>(&postf [((size_t)t * BATCH + b) * 2048 + col]) = nd4;
  else if (chain == 3)
    *reinterpret_cast<float4*>(&priorf[((size_t)t * BATCH + b) * 2048 + col]) = nd4;
}

// ---------------- sample kernel: threefry + gumbel argmax -> idx (+ one-hot feats) ----
__global__ __launch_bounds__(128) void sample_k(const float* __restrict__ st0,
                                                const float* __restrict__ st1,
                                                float* __restrict__ postf,
                                                float* __restrict__ priorf,
                                                int t) {
  const int warp = blockIdx.x * 4 + (threadIdx.x >> 5);  // 0..16383
  const int lane = threadIdx.x & 31;
  const int chain = warp >> 12;
  const int bs = warp & 4095;
  const int b = bs >> 5, s = bs & 31;

  int tt = t + (chain == 0 ? 0 : chain == 1 ? 128 : chain == 2 ? 256 : 320);
  unsigned fk0, fk1;
  tf2x32(0u, 7u, 0u, (unsigned)tt, fk0, fk1);

  const unsigned i = (unsigned)(b * 1024 + s * 32 + lane);  // flat (B,S,D)
  unsigned bits;
#if JAX_PARTITIONABLE
  { unsigned o0, o1; tf2x32(fk0, fk1, 0u, i, o0, o1); bits = o0 ^ o1; }
#else
  { unsigned j = (i < 65536u) ? i : (i - 65536u);
    unsigned o0, o1; tf2x32(fk0, fk1, j, j + 65536u, o0, o1);
    bits = (i < 65536u) ? o0 : o1; }
#endif
  float u = __uint_as_float((bits >> 9) | 0x3f800000u) - 1.0f;
  if (u == 0.0f) u = 1.17549435e-38f;   // jnp.finfo(f32).tiny
  float gmb = -logf(-logf(u));

  const float* st = (chain == 0) ? st0 : (chain == 1) ? st1 : &g_stats[chain][0][0];
  float val = st[i] + gmb;

  float bv = val; int bi = lane;
#pragma unroll
  for (int off = 16; off; off >>= 1) {
    float ov = __shfl_down_sync(0xffffffffu, bv, off);
    int   oi = __shfl_down_sync(0xffffffffu, bi, off);
    if (ov > bv || (ov == bv && oi < bi)) { bv = ov; bi = oi; }
  }
  bi = __shfl_sync(0xffffffffu, bi, 0);

  if (lane == 0) g_idx[chain][b][s] = bi;
  if (chain >= 2) {
    float oh = (lane == bi) ? 1.0f : 0.0f;
    float* dst = (chain == 2) ? postf : priorf;
    dst[((size_t)t * BATCH + b) * 2048 + 1024 + s * 32 + lane] = oh;
  }
}

// ---------------- init: zero recurrent state, idx sentinel ----------------
__global__ void init_k() {
  size_t n = (size_t)NCHAIN * BATCH * HDIM;
  size_t idx = (size_t)blockIdx.x * blockDim.x + threadIdx.x;
  if (idx < n) (&g_deter[0][0][0])[idx] = 0.f;
  if (idx < (size_t)NCHAIN * BATCH * 32) (&g_idx[0][0][0])[idx] = -1;
}

// ---------------- host orchestration ----------------
extern "C" void kernel_launch(void* const* d_in, const int* in_sizes, int n_in,
                              void* d_out, int out_size) {
  (void)in_sizes; (void)n_in; (void)out_size;
  const float* embeds   = (const float*)d_in[0];
  const float* actions  = (const float*)d_in[1];
  const float* w_pre    = (const float*)d_in[2];
  const float* b_pre    = (const float*)d_in[3];
  const float* w_gru    = (const float*)d_in[4];
  const float* b_gru    = (const float*)d_in[5];
  const float* ln_scale = (const float*)d_in[6];
  const float* ln_offset= (const float*)d_in[7];
  const float* w_prior1 = (const float*)d_in[8];
  const float* b_prior1 = (const float*)d_in[9];
  const float* w_prior2 = (const float*)d_in[10];
  const float* b_prior2 = (const float*)d_in[11];
  const float* w_post1  = (const float*)d_in[12];
  const float* b_post1  = (const float*)d_in[13];
  const float* w_post2  = (const float*)d_in[14];
  const float* b_post2  = (const float*)d_in[15];

  float* out    = (float*)d_out;
  float* priors = out;
  float* posts  = priors + (size_t)T_STEPS * BATCH * 1024;
  float* postf  = posts  + (size_t)T_STEPS * BATCH * 1024;
  float* priorf = postf  + (size_t)T_STEPS * BATCH * 2048;

  float *p_deter, *p_x, *p_g, *p_h1, *p_stats;
  cudaGetSymbolAddress((void**)&p_deter, g_deter);
  cudaGetSymbolAddress((void**)&p_x,     g_x);
  cudaGetSymbolAddress((void**)&p_g,     g_g);
  cudaGetSymbolAddress((void**)&p_h1,    g_h1);
  cudaGetSymbolAddress((void**)&p_stats, g_stats);

  init_k<<<(NCHAIN * BATCH * HDIM + 255) / 256, 256>>>();

  for (int t = 0; t < T_STEPS; t++) {
    // ---- pre: x = elu([stoch | act_t] @ w_pre + b_pre) via one-hot gather
    pre_k<<<NCHAIN * BATCH, 256>>>(actions + (size_t)t * BATCH * A_DIM, w_pre, b_pre);

    // ---- gru linear: g = [x | deter] @ w_gru + b_gru, M=512, K=2048, N=3072
    {
      GemmParams p = {};
      p.a[0].A1 = p_x; p.a[0].A2 = p_deter;
      p.a[0].W = w_gru; p.a[0].bias = b_gru; p.a[0].C = p_g;
      p.a[0].k1 = 1024; p.a[0].K = 2048;
      p.N = 3072; p.lda1 = 1024; p.lda2 = 1024; p.act = 0;
      gemm_k<<<dim3(3072 / BN, 512 / BM, 1), 128>>>(p);
    }
    // ---- LN + gates -> deter (and nd -> features for chains 2,3)
    gate_k<<<NCHAIN * BATCH, 256>>>(ln_scale, ln_offset, postf, priorf, t);

    // ---- stats layer 1 (per chain): prior chains K=1024, post chains K=2048
    {
      GemmParams p = {};
      for (int c = 0; c < 4; c++) {
        p.a[c].A1 = p_deter + (size_t)c * BATCH * HDIM;
        p.a[c].C  = p_h1    + (size_t)c * BATCH * HDIM;
        if (c == 0 || c == 3) {  // prior chains
          p.a[c].A2 = nullptr; p.a[c].k1 = 1024; p.a[c].K = 1024;
          p.a[c].W = w_prior1; p.a[c].bias = b_prior1;
        } else {                 // post chains: [deter | emb_t]
          p.a[c].A2 = embeds + (size_t)t * BATCH * EMBED;
          p.a[c].k1 = 1024; p.a[c].K = 2048;
          p.a[c].W = w_post1; p.a[c].bias = b_post1;
        }
      }
      p.N = 1024; p.lda1 = 1024; p.lda2 = 1024; p.act = 1;
      gemm_k<<<dim3(1024 / BN, BATCH / BM, 4), 128>>>(p);
    }
    // ---- stats layer 2 (per chain): stats = h1 @ w2 + b2
    {
      GemmParams p = {};
      for (int c = 0; c < 4; c++) {
        p.a[c].A1 = p_h1 + (size_t)c * BATCH * HDIM;
        p.a[c].A2 = nullptr; p.a[c].k1 = 1024; p.a[c].K = 1024;
        if (c == 0 || c == 3) { p.a[c].W = w_prior2; p.a[c].bias = b_prior2; }
        else                  { p.a[c].W = w_post2;  p.a[c].bias = b_post2;  }
      }
      p.a[0].C = priors + (size_t)t * BATCH * 1024;
      p.a[1].C = posts  + (size_t)t * BATCH * 1024;
      p.a[2].C = p_stats + (size_t)2 * BATCH * DIST;
      p.a[3].C = p_stats + (size_t)3 * BATCH * DIST;
      p.N = 1024; p.lda1 = 1024; p.lda2 = 1024; p.act = 0;
      gemm_k<<<dim3(1024 / BN, BATCH / BM, 4), 128>>>(p);
    }
    // ---- sample: threefry gumbel argmax -> idx (+ one-hot features)
    sample_k<<<4096, 128>>>(priors + (size_t)t * BATCH * 1024,
                            posts  + (size_t)t * BATCH * 1024,
                            postf, priorf, t);
  }
}